// round 1
// baseline (speedup 1.0000x reference)
#include <cuda_runtime.h>
#include <cstdint>
#include <cstddef>

// Problem shape (fixed by the dataset)
#define BB   8
#define T1C  2048
#define T2C  2048
#define DD   256

// GEMM tiling
#define BM   128
#define BN   128
#define BK   32
#define BMP  132   // padded row for As[k][i]
#define BNP  132   // padded row for Bs[k][j]
#define SMEM_FLOATS (DD * BMP + 2 * BK * BNP)

__device__ int g_argmax[BB * T1C];

static __device__ __forceinline__ unsigned long long pk2(float lo, float hi) {
    unsigned long long r;
    asm("mov.b64 %0, {%1, %2};" : "=l"(r) : "f"(lo), "f"(hi));
    return r;
}
static __device__ __forceinline__ unsigned long long fma2(unsigned long long a,
                                                          unsigned long long b,
                                                          unsigned long long c) {
    unsigned long long d;
    asm("fma.rn.f32x2 %0, %1, %2, %3;" : "=l"(d) : "l"(a), "l"(b), "l"(c));
    return d;
}
static __device__ __forceinline__ void upk2(unsigned long long v, float& lo, float& hi) {
    asm("mov.b64 {%0, %1}, %2;" : "=f"(lo), "=f"(hi) : "l"(v));
}

// One CTA per (b, 128-row i-tile). Streams all of s2[b] through smem in
// 128x32 chunks, keeps the full 128x256 s1 tile resident in smem, and tracks
// a running (max, argmin-index-of-max) per i-row. Micro-tile per thread:
// 16 i-rows (as 8 packed f32x2 pairs) x 4 j-cols, computed with fma.rn.f32x2.
__global__ void __launch_bounds__(256, 1)
argmax_gemm_kernel(const float* __restrict__ s1, const float* __restrict__ s2)
{
    extern __shared__ float smem[];
    float* As = smem;                 // [DD][BMP]  (k-major, i contiguous)
    float* Bs = smem + DD * BMP;      // [2][BK][BNP]

    const int tid = threadIdx.x;
    const int b   = blockIdx.y;
    const int i0  = blockIdx.x * BM;
    const int ti  = tid >> 5;         // 0..7  -> i group of 16 (whole warp shares ti)
    const int tj  = tid & 31;         // lane  -> j group of 4

    const float* s1b = s1 + ((size_t)b * T1C + i0) * DD;
    const float* s2b = s2 + (size_t)b * T2C * DD;

    // Stage the full A tile transposed: As[k][i]
    #pragma unroll
    for (int r = 0; r < (BM * DD / 4) / 256; r++) {
        int f  = tid + 256 * r;
        int i  = f >> 6;              // f / (DD/4)
        int kq = f & 63;
        float4 v = ((const float4*)s1b)[(size_t)i * (DD / 4) + kq];
        int k = kq * 4;
        As[(k + 0) * BMP + i] = v.x;
        As[(k + 1) * BMP + i] = v.y;
        As[(k + 2) * BMP + i] = v.z;
        As[(k + 3) * BMP + i] = v.w;
    }

    float best_val[16];
    int   best_idx[16];
    #pragma unroll
    for (int ii = 0; ii < 16; ii++) {
        best_val[ii] = __int_as_float(0xff800000);  // -inf
        best_idx[ii] = 0;
    }

    for (int jc = 0; jc < T2C / BN; jc++) {
        const int j0 = jc * BN;

        // Prefetch k-chunk 0 of this j-tile and stage into buffer 0.
        float4 rB[4];
        #pragma unroll
        for (int r = 0; r < 4; r++) {
            int f  = tid + 256 * r;
            int j  = f >> 3;
            int kq = f & 7;
            rB[r] = ((const float4*)(s2b + (size_t)(j0 + j) * DD))[kq];
        }
        #pragma unroll
        for (int r = 0; r < 4; r++) {
            int f = tid + 256 * r;
            int j = f >> 3;
            int k = (f & 7) * 4;
            Bs[(k + 0) * BNP + j] = rB[r].x;
            Bs[(k + 1) * BNP + j] = rB[r].y;
            Bs[(k + 2) * BNP + j] = rB[r].z;
            Bs[(k + 3) * BNP + j] = rB[r].w;
        }

        unsigned long long acc[8][4];
        #pragma unroll
        for (int p = 0; p < 8; p++)
            #pragma unroll
            for (int q = 0; q < 4; q++) acc[p][q] = 0ull;

        #pragma unroll 1
        for (int kc = 0; kc < DD / BK; kc++) {
            __syncthreads();  // makes the most recent Bs stores visible
            const int buf = kc & 1;

            // Prefetch next k-chunk from global while computing this one.
            if (kc < DD / BK - 1) {
                const int kbase = (kc + 1) * (BK / 4);
                #pragma unroll
                for (int r = 0; r < 4; r++) {
                    int f  = tid + 256 * r;
                    int j  = f >> 3;
                    int kq = f & 7;
                    rB[r] = ((const float4*)(s2b + (size_t)(j0 + j) * DD))[kbase + kq];
                }
            }

            const float* Asb = As + (size_t)kc * BK * BMP + ti * 16;
            const float* Bsb = Bs + buf * BK * BNP + tj * 4;
            #pragma unroll
            for (int kk = 0; kk < BK; kk++) {
                const float* ar = Asb + kk * BMP;
                ulonglong2 a01 = *(const ulonglong2*)(ar);
                ulonglong2 a23 = *(const ulonglong2*)(ar + 4);
                ulonglong2 a45 = *(const ulonglong2*)(ar + 8);
                ulonglong2 a67 = *(const ulonglong2*)(ar + 12);
                unsigned long long ap[8] = {a01.x, a01.y, a23.x, a23.y,
                                            a45.x, a45.y, a67.x, a67.y};
                float4 bv = *(const float4*)(Bsb + kk * BNP);
                unsigned long long bd[4] = {pk2(bv.x, bv.x), pk2(bv.y, bv.y),
                                            pk2(bv.z, bv.z), pk2(bv.w, bv.w)};
                #pragma unroll
                for (int p = 0; p < 8; p++)
                    #pragma unroll
                    for (int q = 0; q < 4; q++)
                        acc[p][q] = fma2(ap[p], bd[q], acc[p][q]);
            }

            // Stage prefetched chunk into the other buffer. Safe without an
            // extra barrier: its previous readers finished before the
            // __syncthreads() at the top of this iteration, and its next
            // readers wait on the top barrier of the next iteration.
            if (kc < DD / BK - 1) {
                float* dst = Bs + (buf ^ 1) * BK * BNP;
                #pragma unroll
                for (int r = 0; r < 4; r++) {
                    int f = tid + 256 * r;
                    int j = f >> 3;
                    int k = (f & 7) * 4;
                    dst[(k + 0) * BNP + j] = rB[r].x;
                    dst[(k + 1) * BNP + j] = rB[r].y;
                    dst[(k + 2) * BNP + j] = rB[r].z;
                    dst[(k + 3) * BNP + j] = rB[r].w;
                }
            }
        }

        // Fold this j-tile's scores into the running argmax.
        // j ascends with q and jc, so strict '>' keeps the FIRST max (numpy tie rule).
        #pragma unroll
        for (int p = 0; p < 8; p++) {
            #pragma unroll
            for (int q = 0; q < 4; q++) {
                float lo, hi;
                upk2(acc[p][q], lo, hi);
                int jg = j0 + tj * 4 + q;
                if (lo > best_val[2 * p])     { best_val[2 * p]     = lo; best_idx[2 * p]     = jg; }
                if (hi > best_val[2 * p + 1]) { best_val[2 * p + 1] = hi; best_idx[2 * p + 1] = jg; }
            }
        }
    }

    // Warp-wide argmax reduce (all 32 lanes of a warp share the same 16 i-rows).
    #pragma unroll
    for (int ii = 0; ii < 16; ii++) {
        float v  = best_val[ii];
        int   ji = best_idx[ii];
        #pragma unroll
        for (int off = 16; off > 0; off >>= 1) {
            float v2 = __shfl_xor_sync(0xffffffffu, v, off);
            int   j2 = __shfl_xor_sync(0xffffffffu, ji, off);
            if (v2 > v || (v2 == v && j2 < ji)) { v = v2; ji = j2; }
        }
        if (tj == 0)
            g_argmax[b * T1C + i0 + ti * 16 + ii] = ji;
    }
}

// One warp per (b, i) row: gathers s2[b, idx, :] into u_tile and writes the
// single 1.0f of the one-hot row (region pre-zeroed by cudaMemsetAsync).
__global__ void __launch_bounds__(256)
gather_onehot_kernel(const float* __restrict__ s2, float* __restrict__ out)
{
    const int wid  = threadIdx.x >> 5;
    const int lane = threadIdx.x & 31;
    const int r    = blockIdx.x * 8 + wid;   // 0 .. BB*T1C-1
    const int b    = r >> 11;
    const int i    = r & (T1C - 1);
    const int j    = g_argmax[r];

    const float4* src = (const float4*)(s2 + ((size_t)b * T2C + (size_t)j) * DD);
    float4*       dst = (float4*)(out + (size_t)r * DD);
    dst[lane]      = src[lane];
    dst[lane + 32] = src[lane + 32];

    if (lane == 0)
        out[(size_t)BB * T1C * DD + (size_t)b * T1C * T2C + (size_t)i * T2C + j] = 1.0f;
}

extern "C" void kernel_launch(void* const* d_in, const int* in_sizes, int n_in,
                              void* d_out, int out_size)
{
    (void)in_sizes; (void)n_in; (void)out_size;
    const float* s1 = (const float*)d_in[0];
    const float* s2 = (const float*)d_in[1];
    float* out = (float*)d_out;

    const size_t smem_bytes = (size_t)SMEM_FLOATS * sizeof(float);
    cudaFuncSetAttribute(argmax_gemm_kernel,
                         cudaFuncAttributeMaxDynamicSharedMemorySize,
                         (int)smem_bytes);

    dim3 grid(T1C / BM, BB);
    argmax_gemm_kernel<<<grid, 256, smem_bytes>>>(s1, s2);

    // Zero the one-hot region (u_tile region is fully overwritten by the gather).
    cudaMemsetAsync(out + (size_t)BB * T1C * DD, 0,
                    (size_t)BB * T1C * T2C * sizeof(float));

    gather_onehot_kernel<<<(BB * T1C) / 8, 256>>>(s2, out);
}